// round 3
// baseline (speedup 1.0000x reference)
#include <cuda_runtime.h>
#include <math.h>

#define N_NODES 4096
#define C_COMM  32
#define T_DIM   16
#define TOK     (32*4096*16)   // 2097152

// scratch (no allocations allowed)
__device__ float g_G[C_COMM * 64];
__device__ int   g_cls[N_NODES];

// ============================================================================
// Kernel 1: spectral-filtered graphs G_c = Re(V diag(lam*mask) V^-1) = p(A)
// via fp64 Hessenberg + Francis QR eigenvalues + Newton interpolation Horner.
// One matrix per block (1 thread), 32 blocks. Hard iteration cap: terminates.
// ============================================================================
__global__ void eig_kernel(const float* __restrict__ koop)
{
    int c = blockIdx.x;
    if (threadIdx.x != 0) return;

    double a[8][8], A0[8][8];
    for (int i = 0; i < 8; i++)
        for (int j = 0; j < 8; j++) {
            double v = (double)koop[c * 64 + i * 8 + j];
            a[i][j] = v; A0[i][j] = v;
        }

    // ---- Householder reduction to upper Hessenberg (no Q needed) ----
    for (int k = 0; k < 6; k++) {
        double nx = 0.0;
        for (int i = k + 1; i < 8; i++) nx += a[i][k] * a[i][k];
        nx = sqrt(nx);
        if (nx < 1e-300) continue;
        double x0 = a[k + 1][k];
        double alpha = (x0 >= 0.0) ? -nx : nx;
        double v[8];
        for (int i = 0; i < 8; i++) v[i] = 0.0;
        v[k + 1] = x0 - alpha;
        for (int i = k + 2; i < 8; i++) v[i] = a[i][k];
        double vv = 0.0;
        for (int i = k + 1; i < 8; i++) vv += v[i] * v[i];
        if (vv < 1e-300) continue;
        double beta = 2.0 / vv;
        for (int j = 0; j < 8; j++) {
            double s = 0.0;
            for (int i = k + 1; i < 8; i++) s += v[i] * a[i][j];
            s *= beta;
            for (int i = k + 1; i < 8; i++) a[i][j] -= v[i] * s;
        }
        for (int i = 0; i < 8; i++) {
            double s = 0.0;
            for (int j = k + 1; j < 8; j++) s += a[i][j] * v[j];
            s *= beta;
            for (int j = k + 1; j < 8; j++) a[i][j] -= s * v[j];
        }
    }

    // ---- Francis double-shift QR (NR hqr, 0-indexed) -> eigenvalues ----
    double wr[8], wi[8];
    double anorm = 0.0;
    for (int i = 0; i < 8; i++) {
        int j0 = (i - 1 > 0) ? (i - 1) : 0;
        for (int j = j0; j < 8; j++) anorm += fabs(a[i][j]);
    }
    const double EPSD = 2.220446e-16;
    int nn = 7;
    double t = 0.0;
    int guard = 0;                 // hard termination cap (de-risk hangs)
    while (nn >= 0 && guard < 2000) {
        int its = 0;
        int l = 0;
        do {
            guard++;
            if (guard >= 2000) { wr[nn] = a[nn][nn] + t; wi[nn] = 0.0; nn--; break; }
            for (l = nn; l >= 1; l--) {
                double s = fabs(a[l - 1][l - 1]) + fabs(a[l][l]);
                if (s == 0.0) s = anorm;
                if (fabs(a[l][l - 1]) <= EPSD * s) { a[l][l - 1] = 0.0; break; }
            }
            if (l < 0) l = 0;
            double x = a[nn][nn];
            if (l == nn) {
                wr[nn] = x + t; wi[nn] = 0.0; nn--;
            } else {
                double y = a[nn - 1][nn - 1];
                double w = a[nn][nn - 1] * a[nn - 1][nn];
                if (l == nn - 1) {
                    double p = 0.5 * (y - x);
                    double q = p * p + w;
                    double z = sqrt(fabs(q));
                    x += t;
                    if (q >= 0.0) {
                        z = p + ((p >= 0.0) ? z : -z);
                        wr[nn - 1] = wr[nn] = x + z;
                        if (z != 0.0) wr[nn] = x - w / z;
                        wi[nn - 1] = wi[nn] = 0.0;
                    } else {
                        wr[nn - 1] = wr[nn] = x + p;
                        wi[nn] = z; wi[nn - 1] = -z;
                    }
                    nn -= 2;
                } else {
                    double p = 0.0, q = 0.0, r = 0.0, z, s, u, v;
                    if (its == 10 || its == 20) {
                        t += x;
                        for (int i = 0; i <= nn; i++) a[i][i] -= x;
                        s = fabs(a[nn][nn - 1]) + fabs(a[nn - 1][nn - 2]);
                        y = x = 0.75 * s;
                        w = -0.4375 * s * s;
                    }
                    its++;
                    if (its > 50) { wr[nn] = a[nn][nn] + t; wi[nn] = 0.0; nn--; break; }
                    int m;
                    for (m = nn - 2; m >= l; m--) {
                        z = a[m][m];
                        r = x - z;
                        s = y - z;
                        p = (r * s - w) / a[m + 1][m] + a[m][m + 1];
                        q = a[m + 1][m + 1] - z - r - s;
                        r = a[m + 2][m + 1];
                        s = fabs(p) + fabs(q) + fabs(r);
                        p /= s; q /= s; r /= s;
                        if (m == l) break;
                        u = fabs(a[m][m - 1]) * (fabs(q) + fabs(r));
                        v = fabs(p) * (fabs(a[m - 1][m - 1]) + fabs(z) + fabs(a[m + 1][m + 1]));
                        if (u <= EPSD * v) break;
                    }
                    for (int i = m + 2; i <= nn; i++) {
                        a[i][i - 2] = 0.0;
                        if (i != m + 2) a[i][i - 3] = 0.0;
                    }
                    for (int k = m; k <= nn - 1; k++) {
                        if (k != m) {
                            p = a[k][k - 1];
                            q = a[k + 1][k - 1];
                            r = 0.0;
                            if (k != nn - 1) r = a[k + 2][k - 1];
                            x = fabs(p) + fabs(q) + fabs(r);
                            if (x != 0.0) { p /= x; q /= x; r /= x; }
                        }
                        s = sqrt(p * p + q * q + r * r);
                        if (p < 0.0) s = -s;
                        if (s != 0.0) {
                            if (k == m) {
                                if (l != m) a[k][k - 1] = -a[k][k - 1];
                            } else a[k][k - 1] = -s * x;
                            p += s; x = p / s; y = q / s; z = r / s; q /= p; r /= p;
                            for (int j = k; j <= nn; j++) {
                                double pp = a[k][j] + q * a[k + 1][j];
                                if (k != nn - 1) { pp += r * a[k + 2][j]; a[k + 2][j] -= pp * z; }
                                a[k + 1][j] -= pp * y;
                                a[k][j]     -= pp * x;
                            }
                            int mmin = (nn < k + 3) ? nn : (k + 3);
                            for (int i = l; i <= mmin; i++) {
                                double pp = x * a[i][k] + y * a[i][k + 1];
                                if (k != nn - 1) { pp += z * a[i][k + 2]; a[i][k + 2] -= pp * r; }
                                a[i][k + 1] -= pp * q;
                                a[i][k]     -= pp;
                            }
                        }
                    }
                }
            }
        } while (l < nn - 1);
    }

    // ---- mask + Newton interpolation of f(lam)=lam*mask, then p(A) ----
    double zr[8], zi[8];
    for (int i = 0; i < 8; i++) { zr[i] = wr[i] + 1e-10; zi[i] = wi[i] + 1e-10; }
    bool mask[8]; bool any = false;
    for (int i = 0; i < 8; i++) {
        double am = sqrt(zr[i] * zr[i] + zi[i] * zi[i]);
        mask[i] = (am <= 1.1 && am >= 0.9);
        any = any || mask[i];
    }
    if (!any) for (int i = 0; i < 8; i++) mask[i] = true;
    // tie-break coincident interpolation nodes (harmless O(1e-8) perturbation)
    for (int i = 1; i < 8; i++)
        for (int j = 0; j < i; j++)
            if (fabs(zr[i] - zr[j]) < 1e-9 && fabs(zi[i] - zi[j]) < 1e-9) {
                zr[i] += 1.0e-8 * (i + 1);
                zi[i] += 0.7e-8 * (i + 1);
            }
    double cr[8], ci[8];
    for (int i = 0; i < 8; i++) {
        cr[i] = mask[i] ? zr[i] : 0.0;
        ci[i] = mask[i] ? zi[i] : 0.0;
    }
    // divided differences (complex)
    for (int j = 1; j < 8; j++)
        for (int i = 7; i >= j; i--) {
            double nr = cr[i] - cr[i - 1], ni = ci[i] - ci[i - 1];
            double dr = zr[i] - zr[i - j], di = zi[i] - zi[i - j];
            double d2 = dr * dr + di * di;
            cr[i] = (nr * dr + ni * di) / d2;
            ci[i] = (ni * dr - nr * di) / d2;
        }
    // Horner: M = c7*I; M = (A - z_k I) M + c_k I
    double Mr[8][8], Mi[8][8];
    for (int i = 0; i < 8; i++)
        for (int j = 0; j < 8; j++) {
            Mr[i][j] = (i == j) ? cr[7] : 0.0;
            Mi[i][j] = (i == j) ? ci[7] : 0.0;
        }
    for (int k = 6; k >= 0; k--) {
        double Tr[8][8], Ti[8][8];
        for (int i = 0; i < 8; i++)
            for (int j = 0; j < 8; j++) {
                double sr = 0.0, si = 0.0;
                for (int q = 0; q < 8; q++) {
                    sr += A0[i][q] * Mr[q][j];
                    si += A0[i][q] * Mi[q][j];
                }
                Tr[i][j] = sr; Ti[i][j] = si;
            }
        for (int i = 0; i < 8; i++)
            for (int j = 0; j < 8; j++) {
                double mr = Tr[i][j] - (zr[k] * Mr[i][j] - zi[k] * Mi[i][j]);
                double mi = Ti[i][j] - (zr[k] * Mi[i][j] + zi[k] * Mr[i][j]);
                if (i == j) { mr += cr[k]; mi += ci[k]; }
                Mr[i][j] = mr; Mi[i][j] = mi;
            }
    }
    for (int i = 0; i < 8; i++)
        for (int j = 0; j < 8; j++)
            g_G[c * 64 + i * 8 + j] = (float)Mr[i][j];
}

// ============================================================================
// Kernel 2: community argmax (first-max, matching jnp.argmax)
// ============================================================================
__global__ void argmax_kernel(const float* __restrict__ comm)
{
    int n = blockIdx.x * blockDim.x + threadIdx.x;
    if (n >= N_NODES) return;
    float best = comm[n * C_COMM];
    int bi = 0;
#pragma unroll
    for (int cc = 1; cc < C_COMM; cc++) {
        float v = comm[n * C_COMM + cc];
        if (v > best) { best = v; bi = cc; }
    }
    g_cls[n] = bi;
}

// ============================================================================
// Kernel 3: main fused flow. One thread per (b,n,t) token.
// Weights + G table in shared (broadcast LDS.128), h0[64] in registers.
// ============================================================================
#define SM_W0 0
#define SM_B0 2304
#define SM_W1 2496
#define SM_B1 14784
#define SM_W2 14976
#define SM_B2 16512
#define SM_G  16536
#define SM_FLOATS 18584

__device__ __forceinline__ float4 fma4(float a, float4 b, float4 c) {
    c.x = fmaf(a, b.x, c.x);
    c.y = fmaf(a, b.y, c.y);
    c.z = fmaf(a, b.z, c.z);
    c.w = fmaf(a, b.w, c.w);
    return c;
}

__global__ __launch_bounds__(256) void main_kernel(
    const float* __restrict__ latent,
    const float* __restrict__ W0, const float* __restrict__ b0,
    const float* __restrict__ W1, const float* __restrict__ b1,
    const float* __restrict__ W2, const float* __restrict__ b2,
    float* __restrict__ out)
{
    extern __shared__ float smem[];
    const int tx = threadIdx.x;

    for (int i = tx; i < 2304;  i += 256) smem[SM_W0 + i] = W0[i];
    for (int i = tx; i < 192;   i += 256) smem[SM_B0 + i] = b0[i];
    for (int i = tx; i < 12288; i += 256) smem[SM_W1 + i] = W1[i];
    for (int i = tx; i < 192;   i += 256) smem[SM_B1 + i] = b1[i];
    for (int i = tx; i < 1536;  i += 256) smem[SM_W2 + i] = W2[i];
    for (int i = tx; i < 24;    i += 256) smem[SM_B2 + i] = b2[i];
    for (int i = tx; i < 2048;  i += 256) smem[SM_G  + i] = g_G[i];
    __syncthreads();

    const int tid = blockIdx.x * 256 + tx;
    const int n = (tid >> 4) & (N_NODES - 1);
    const int cls = g_cls[n];

    float x[8];
    {
        const float4* lat4 = reinterpret_cast<const float4*>(latent);
        float4 p0 = lat4[tid * 2];
        float4 p1 = lat4[tid * 2 + 1];
        x[0] = p0.x; x[1] = p0.y; x[2] = p0.z; x[3] = p0.w;
        x[4] = p1.x; x[5] = p1.y; x[6] = p1.z; x[7] = p1.w;
    }

    // cond[e] = sum_d x[d] * G[cls][d][e]
    float cond[8];
    {
        const float4* sG = reinterpret_cast<const float4*>(smem + SM_G) + cls * 16;
        float4 c0 = make_float4(0.f, 0.f, 0.f, 0.f);
        float4 c1 = make_float4(0.f, 0.f, 0.f, 0.f);
#pragma unroll
        for (int d = 0; d < 8; d++) {
            float xd = x[d];
            c0 = fma4(xd, sG[d * 2], c0);
            c1 = fma4(xd, sG[d * 2 + 1], c1);
        }
        cond[0] = c0.x; cond[1] = c0.y; cond[2] = c0.z; cond[3] = c0.w;
        cond[4] = c1.x; cond[5] = c1.y; cond[6] = c1.z; cond[7] = c1.w;
    }

    float logdet = 0.f;
#pragma unroll
    for (int blk = 0; blk < 3; blk++) {
        const float4* w0  = reinterpret_cast<const float4*>(smem + SM_W0) + blk * 192;
        const float4* bb0 = reinterpret_cast<const float4*>(smem + SM_B0) + blk * 16;
        const float4* w1  = reinterpret_cast<const float4*>(smem + SM_W1) + blk * 1024;
        const float4* bb1 = reinterpret_cast<const float4*>(smem + SM_B1) + blk * 16;
        const float4* w2  = reinterpret_cast<const float4*>(smem + SM_W2) + blk * 128;
        const float*  bb2 = smem + SM_B2 + blk * 8;

        const int off1 = (blk & 1) ? 4 : 0;  // x1 (input half)
        const int off2 = 4 - off1;           // x2 (transformed half)

        float in12[12];
#pragma unroll
        for (int q = 0; q < 4; q++) in12[q] = x[off1 + q];
#pragma unroll
        for (int q = 0; q < 8; q++) in12[4 + q] = cond[q];

        // layer 0: 12 -> 64, relu
        float h0[64];
#pragma unroll
        for (int jv = 0; jv < 16; jv++) {
            float4 acc = bb0[jv];
#pragma unroll
            for (int k = 0; k < 12; k++)
                acc = fma4(in12[k], w0[k * 16 + jv], acc);
            h0[jv * 4 + 0] = fmaxf(acc.x, 0.f);
            h0[jv * 4 + 1] = fmaxf(acc.y, 0.f);
            h0[jv * 4 + 2] = fmaxf(acc.z, 0.f);
            h0[jv * 4 + 3] = fmaxf(acc.w, 0.f);
        }

        // layers 1+2 fused: 64 -> 64 (relu) -> 8, h1 never materialized fully
        float4 oA = make_float4(bb2[0], bb2[1], bb2[2], bb2[3]);
        float4 oB = make_float4(bb2[4], bb2[5], bb2[6], bb2[7]);
#pragma unroll
        for (int jv = 0; jv < 16; jv++) {
            float4 acc = bb1[jv];
#pragma unroll
            for (int k = 0; k < 64; k++)
                acc = fma4(h0[k], w1[k * 16 + jv], acc);
            float hv[4];
            hv[0] = fmaxf(acc.x, 0.f);
            hv[1] = fmaxf(acc.y, 0.f);
            hv[2] = fmaxf(acc.z, 0.f);
            hv[3] = fmaxf(acc.w, 0.f);
#pragma unroll
            for (int q = 0; q < 4; q++) {
                int j = jv * 4 + q;
                oA = fma4(hv[q], w2[j * 2], oA);
                oB = fma4(hv[q], w2[j * 2 + 1], oB);
            }
        }

        float s0 = tanhf(oA.x), s1 = tanhf(oA.y), s2 = tanhf(oA.z), s3 = tanhf(oA.w);
        logdet += s0 + s1 + s2 + s3;
        x[off2 + 0] = x[off2 + 0] * expf(s0) + oB.x;
        x[off2 + 1] = x[off2 + 1] * expf(s1) + oB.y;
        x[off2 + 2] = x[off2 + 2] * expf(s2) + oB.z;
        x[off2 + 3] = x[off2 + 3] * expf(s3) + oB.w;
    }

    float ss = 0.f;
#pragma unroll
    for (int q = 0; q < 8; q++) ss += x[q] * x[q];

    out[tid] = -0.5f * ss - 7.3515082656f + logdet;
}

// ============================================================================
extern "C" void kernel_launch(void* const* d_in, const int* in_sizes, int n_in,
                              void* d_out, int out_size)
{
    const float* latent = (const float*)d_in[0];
    const float* koop   = (const float*)d_in[1];
    const float* comm   = (const float*)d_in[2];
    const float* W0     = (const float*)d_in[3];
    const float* b0     = (const float*)d_in[4];
    const float* W1     = (const float*)d_in[5];
    const float* b1     = (const float*)d_in[6];
    const float* W2     = (const float*)d_in[7];
    const float* b2     = (const float*)d_in[8];
    float* out = (float*)d_out;

    eig_kernel<<<C_COMM, 1>>>(koop);
    argmax_kernel<<<N_NODES / 256, 256>>>(comm);

    (void)cudaFuncSetAttribute(main_kernel,
                               cudaFuncAttributeMaxDynamicSharedMemorySize,
                               SM_FLOATS * 4);
    main_kernel<<<TOK / 256, 256, SM_FLOATS * 4>>>(
        latent, W0, b0, W1, b1, W2, b2, out);
}

// round 8
// speedup vs baseline: 2.9319x; 2.9319x over previous
#include <cuda_runtime.h>
#include <cuda_bf16.h>
#include <math.h>
#include <stdint.h>

#define N_NODES 4096
#define C_COMM  32
#define TOK     (32*4096*16)
#define NTILES  (TOK/16)        // 131072 warp-tiles of 16 tokens
#define GRID_CTAS 296
#define NWARPS  (GRID_CTAS*8)   // 2368

// ---------------- device scratch ----------------
__device__ float  g_G[C_COMM * 64];
__device__ int    g_cls[N_NODES];
__device__ double g_zr[C_COMM*8], g_zi[C_COMM*8], g_cr[C_COMM*8], g_ci[C_COMM*8];
// B-fragment tables: [3 blocks][88 pos][32 lanes] x uint2  (67584 B)
__device__ uint2  g_btab[3 * 88 * 32];

// ---------------- smem float layout ----------------
#define F_BTAB 0          // 16896 floats (btab as raw)
#define F_B0   16896      // 192
#define F_B1   17088      // 192
#define F_B2   17280      // 24
#define F_G    17304      // 2048
#define F_SIN  19352      // 8 warps x 16 x 16
#define F_SD   21400      // 8 warps x 16 x 8
#define SMEM_FLOATS 22424
#define SMEM_TOTAL  (SMEM_FLOATS*4)

#define MMA4(D, A, B0, B1) asm volatile( \
    "mma.sync.aligned.m16n8k16.row.col.f32.bf16.bf16.f32 " \
    "{%0,%1,%2,%3},{%4,%5,%6,%7},{%8,%9},{%0,%1,%2,%3};" \
    : "+f"((D)[0]), "+f"((D)[1]), "+f"((D)[2]), "+f"((D)[3]) \
    : "r"((A)[0]), "r"((A)[1]), "r"((A)[2]), "r"((A)[3]), "r"(B0), "r"(B1))

// split v = hi + lo (hi = truncate-to-bf16, lo = bf16 residual); pack pairs
__device__ __forceinline__ void splitpack(float v0, float v1, uint32_t& hi, uint32_t& lo) {
    uint32_t u0 = __float_as_uint(v0), u1 = __float_as_uint(v1);
    hi = __byte_perm(u0, u1, 0x7632);
    float h0 = __uint_as_float(u0 & 0xFFFF0000u);
    float h1 = __uint_as_float(u1 & 0xFFFF0000u);
    asm("cvt.rn.bf16x2.f32 %0, %1, %2;" : "=r"(lo) : "f"(v1 - h1), "f"(v0 - h0));
}

// ============================================================================
// Kernel 1a: fp64 Hessenberg + Francis QR eigenvalues + Newton coeffs
// ============================================================================
__global__ void eig_vals_kernel(const float* __restrict__ koop)
{
    int c = blockIdx.x;
    if (threadIdx.x != 0) return;
    double a[8][8];
    for (int i = 0; i < 8; i++)
        for (int j = 0; j < 8; j++)
            a[i][j] = (double)koop[c * 64 + i * 8 + j];
    for (int k = 0; k < 6; k++) {
        double nx = 0.0;
        for (int i = k + 1; i < 8; i++) nx += a[i][k] * a[i][k];
        nx = sqrt(nx);
        if (nx < 1e-300) continue;
        double x0 = a[k + 1][k];
        double alpha = (x0 >= 0.0) ? -nx : nx;
        double v[8];
        for (int i = 0; i < 8; i++) v[i] = 0.0;
        v[k + 1] = x0 - alpha;
        for (int i = k + 2; i < 8; i++) v[i] = a[i][k];
        double vv = 0.0;
        for (int i = k + 1; i < 8; i++) vv += v[i] * v[i];
        if (vv < 1e-300) continue;
        double beta = 2.0 / vv;
        for (int j = 0; j < 8; j++) {
            double s = 0.0;
            for (int i = k + 1; i < 8; i++) s += v[i] * a[i][j];
            s *= beta;
            for (int i = k + 1; i < 8; i++) a[i][j] -= v[i] * s;
        }
        for (int i = 0; i < 8; i++) {
            double s = 0.0;
            for (int j = k + 1; j < 8; j++) s += a[i][j] * v[j];
            s *= beta;
            for (int j = k + 1; j < 8; j++) a[i][j] -= s * v[j];
        }
    }
    double wr[8], wi[8];
    double anorm = 0.0;
    for (int i = 0; i < 8; i++) {
        int j0 = (i - 1 > 0) ? (i - 1) : 0;
        for (int j = j0; j < 8; j++) anorm += fabs(a[i][j]);
    }
    const double EPSD = 2.220446e-16;
    int nn = 7; double t = 0.0; int guard = 0;
    while (nn >= 0 && guard < 2000) {
        int its = 0, l = 0;
        do {
            guard++;
            if (guard >= 2000) { wr[nn] = a[nn][nn] + t; wi[nn] = 0.0; nn--; break; }
            for (l = nn; l >= 1; l--) {
                double s = fabs(a[l - 1][l - 1]) + fabs(a[l][l]);
                if (s == 0.0) s = anorm;
                if (fabs(a[l][l - 1]) <= EPSD * s) { a[l][l - 1] = 0.0; break; }
            }
            if (l < 0) l = 0;
            double x = a[nn][nn];
            if (l == nn) { wr[nn] = x + t; wi[nn] = 0.0; nn--; }
            else {
                double y = a[nn - 1][nn - 1];
                double w = a[nn][nn - 1] * a[nn - 1][nn];
                if (l == nn - 1) {
                    double p = 0.5 * (y - x);
                    double q = p * p + w;
                    double z = sqrt(fabs(q));
                    x += t;
                    if (q >= 0.0) {
                        z = p + ((p >= 0.0) ? z : -z);
                        wr[nn - 1] = wr[nn] = x + z;
                        if (z != 0.0) wr[nn] = x - w / z;
                        wi[nn - 1] = wi[nn] = 0.0;
                    } else {
                        wr[nn - 1] = wr[nn] = x + p;
                        wi[nn] = z; wi[nn - 1] = -z;
                    }
                    nn -= 2;
                } else {
                    double p = 0.0, q = 0.0, r = 0.0, z, s, u, v;
                    if (its == 10 || its == 20) {
                        t += x;
                        for (int i = 0; i <= nn; i++) a[i][i] -= x;
                        s = fabs(a[nn][nn - 1]) + fabs(a[nn - 1][nn - 2]);
                        y = x = 0.75 * s;
                        w = -0.4375 * s * s;
                    }
                    its++;
                    if (its > 50) { wr[nn] = a[nn][nn] + t; wi[nn] = 0.0; nn--; break; }
                    int m;
                    for (m = nn - 2; m >= l; m--) {
                        z = a[m][m]; r = x - z; s = y - z;
                        p = (r * s - w) / a[m + 1][m] + a[m][m + 1];
                        q = a[m + 1][m + 1] - z - r - s;
                        r = a[m + 2][m + 1];
                        s = fabs(p) + fabs(q) + fabs(r);
                        p /= s; q /= s; r /= s;
                        if (m == l) break;
                        u = fabs(a[m][m - 1]) * (fabs(q) + fabs(r));
                        v = fabs(p) * (fabs(a[m - 1][m - 1]) + fabs(z) + fabs(a[m + 1][m + 1]));
                        if (u <= EPSD * v) break;
                    }
                    for (int i = m + 2; i <= nn; i++) {
                        a[i][i - 2] = 0.0;
                        if (i != m + 2) a[i][i - 3] = 0.0;
                    }
                    for (int k = m; k <= nn - 1; k++) {
                        if (k != m) {
                            p = a[k][k - 1]; q = a[k + 1][k - 1];
                            r = (k != nn - 1) ? a[k + 2][k - 1] : 0.0;
                            x = fabs(p) + fabs(q) + fabs(r);
                            if (x != 0.0) { p /= x; q /= x; r /= x; }
                        }
                        s = sqrt(p * p + q * q + r * r);
                        if (p < 0.0) s = -s;
                        if (s != 0.0) {
                            if (k == m) { if (l != m) a[k][k - 1] = -a[k][k - 1]; }
                            else a[k][k - 1] = -s * x;
                            p += s; x = p / s; y = q / s; z = r / s; q /= p; r /= p;
                            for (int j = k; j <= nn; j++) {
                                double pp = a[k][j] + q * a[k + 1][j];
                                if (k != nn - 1) { pp += r * a[k + 2][j]; a[k + 2][j] -= pp * z; }
                                a[k + 1][j] -= pp * y;
                                a[k][j]     -= pp * x;
                            }
                            int mmin = (nn < k + 3) ? nn : (k + 3);
                            for (int i = l; i <= mmin; i++) {
                                double pp = x * a[i][k] + y * a[i][k + 1];
                                if (k != nn - 1) { pp += z * a[i][k + 2]; a[i][k + 2] -= pp * r; }
                                a[i][k + 1] -= pp * q;
                                a[i][k]     -= pp;
                            }
                        }
                    }
                }
            }
        } while (l < nn - 1);
    }
    double zr[8], zi[8];
    for (int i = 0; i < 8; i++) { zr[i] = wr[i] + 1e-10; zi[i] = wi[i] + 1e-10; }
    bool mask[8]; bool any = false;
    for (int i = 0; i < 8; i++) {
        double am = sqrt(zr[i] * zr[i] + zi[i] * zi[i]);
        mask[i] = (am <= 1.1 && am >= 0.9);
        any = any || mask[i];
    }
    if (!any) for (int i = 0; i < 8; i++) mask[i] = true;
    for (int i = 1; i < 8; i++)
        for (int j = 0; j < i; j++)
            if (fabs(zr[i] - zr[j]) < 1e-9 && fabs(zi[i] - zi[j]) < 1e-9) {
                zr[i] += 1.0e-8 * (i + 1);
                zi[i] += 0.7e-8 * (i + 1);
            }
    double cr[8], ci[8];
    for (int i = 0; i < 8; i++) {
        cr[i] = mask[i] ? zr[i] : 0.0;
        ci[i] = mask[i] ? zi[i] : 0.0;
    }
    for (int j = 1; j < 8; j++)
        for (int i = 7; i >= j; i--) {
            double nr = cr[i] - cr[i - 1], ni = ci[i] - ci[i - 1];
            double dr = zr[i] - zr[i - j], di = zi[i] - zi[i - j];
            double d2 = dr * dr + di * di;
            cr[i] = (nr * dr + ni * di) / d2;
            ci[i] = (ni * dr - nr * di) / d2;
        }
    for (int i = 0; i < 8; i++) {
        g_zr[c * 8 + i] = zr[i]; g_zi[c * 8 + i] = zi[i];
        g_cr[c * 8 + i] = cr[i]; g_ci[c * 8 + i] = ci[i];
    }
}

// ============================================================================
// Kernel 1b: parallel complex Horner p(A) -> G (64 threads per matrix)
// ============================================================================
__global__ void horner_kernel(const float* __restrict__ koop)
{
    int c = blockIdx.x;
    int t = threadIdx.x;
    int i = t >> 3, j = t & 7;
    __shared__ double sA[64], sMr[64], sMi[64], szr[8], szi[8], scr[8], sci[8];
    sA[t] = (double)koop[c * 64 + t];
    if (t < 8) {
        szr[t] = g_zr[c * 8 + t]; szi[t] = g_zi[c * 8 + t];
        scr[t] = g_cr[c * 8 + t]; sci[t] = g_ci[c * 8 + t];
    }
    __syncthreads();
    double mr = (i == j) ? scr[7] : 0.0;
    double mi = (i == j) ? sci[7] : 0.0;
    sMr[t] = mr; sMi[t] = mi;
    __syncthreads();
    for (int k = 6; k >= 0; k--) {
        double tr = 0.0, ti = 0.0;
#pragma unroll
        for (int q = 0; q < 8; q++) {
            tr += sA[i * 8 + q] * sMr[q * 8 + j];
            ti += sA[i * 8 + q] * sMi[q * 8 + j];
        }
        double omr = mr, omi = mi;
        __syncthreads();
        mr = tr - (szr[k] * omr - szi[k] * omi) + ((i == j) ? scr[k] : 0.0);
        mi = ti - (szr[k] * omi + szi[k] * omr) + ((i == j) ? sci[k] : 0.0);
        sMr[t] = mr; sMi[t] = mi;
        __syncthreads();
    }
    g_G[c * 64 + t] = (float)mr;
}

// ============================================================================
// Kernel 2: community argmax
// ============================================================================
__global__ void argmax_kernel(const float* __restrict__ comm)
{
    int n = blockIdx.x * blockDim.x + threadIdx.x;
    if (n >= N_NODES) return;
    float best = comm[n * C_COMM];
    int bi = 0;
#pragma unroll
    for (int cc = 1; cc < C_COMM; cc++) {
        float v = comm[n * C_COMM + cc];
        if (v > best) { best = v; bi = cc; }
    }
    g_cls[n] = bi;
}

// ============================================================================
// Kernel 3: build per-lane B-fragment tables (hi/lo bf16, m16n8k16 layout).
// pos map per coupling block (88 pos): L0: jn*2+v (16) | L1: 16+(jn*4+kb)*2+v
// (64) | L2: 80+kb*2+v (8). Fragment: x = pack(W[k0][n], W[k1][n]),
// y = pack(W[k0+8][n], W[k1+8][n]); n = jn*8+lane/4, k0 = 16*kb+2*(lane%4).
// ============================================================================
__global__ void wprep_kernel(const float* __restrict__ W0,
                             const float* __restrict__ W1,
                             const float* __restrict__ W2)
{
    int blk = blockIdx.x;
    for (int idx = threadIdx.x; idx < 88 * 32; idx += blockDim.x) {
        int pos = idx >> 5, lane = idx & 31;
        int v, jn, kb, layer;
        if (pos < 16)      { layer = 0; v = pos & 1; jn = pos >> 1; kb = 0; }
        else if (pos < 80) { int p = pos - 16; v = p & 1; int q = p >> 1; kb = q & 3; jn = q >> 2; layer = 1; }
        else               { int p = pos - 80; v = p & 1; kb = p >> 1; jn = 0; layer = 2; }
        int n = jn * 8 + (lane >> 2);
        int k0 = 16 * kb + 2 * (lane & 3);
        float w[4];
#pragma unroll
        for (int e = 0; e < 4; e++) {
            int k = k0 + (e >> 1) * 8 + (e & 1);
            float val = 0.f;
            if (layer == 0)      { if (k < 12) val = W0[blk * 768 + k * 64 + n]; }
            else if (layer == 1) { val = W1[blk * 4096 + k * 64 + n]; }
            else                 { val = W2[blk * 512 + k * 8 + n]; }
            __nv_bfloat16 bh = __float2bfloat16(val);
            if (v == 0) w[e] = __bfloat162float(bh);
            else        w[e] = __bfloat162float(__float2bfloat16(val - __bfloat162float(bh)));
        }
        uint32_t px = ((uint32_t)__bfloat16_as_ushort(__float2bfloat16(w[1])) << 16)
                    |  (uint32_t)__bfloat16_as_ushort(__float2bfloat16(w[0]));
        uint32_t py = ((uint32_t)__bfloat16_as_ushort(__float2bfloat16(w[3])) << 16)
                    |  (uint32_t)__bfloat16_as_ushort(__float2bfloat16(w[2]));
        g_btab[(blk * 88 + pos) * 32 + lane] = make_uint2(px, py);
    }
}

// ============================================================================
// Kernel 4: main fused flow via mma.sync bf16x3. Persistent, warp = 16 tokens.
// ============================================================================
__global__ void __launch_bounds__(256, 2) main_kernel(
    const float* __restrict__ latent,
    const float* __restrict__ b0g, const float* __restrict__ b1g,
    const float* __restrict__ b2g, float* __restrict__ out)
{
    extern __shared__ float sm[];
    // prologue: load tables once per CTA
    {
        const uint4* src = reinterpret_cast<const uint4*>(g_btab);
        uint4* dst = reinterpret_cast<uint4*>(sm);
        for (int i = threadIdx.x; i < 16896 / 4; i += 256) dst[i] = src[i];
        for (int i = threadIdx.x; i < 192;  i += 256) sm[F_B0 + i] = b0g[i];
        for (int i = threadIdx.x; i < 192;  i += 256) sm[F_B1 + i] = b1g[i];
        for (int i = threadIdx.x; i < 24;   i += 256) sm[F_B2 + i] = b2g[i];
        for (int i = threadIdx.x; i < 2048; i += 256) sm[F_G + i] = g_G[i];
    }
    __syncthreads();

    const int wid = threadIdx.x >> 5;
    const int lane = threadIdx.x & 31;
    const int r = lane >> 2, qq = lane & 3;
    float* stg = sm + F_SIN + wid * 256;    // [16 tok][16] input staging
    float* sD  = sm + F_SD  + wid * 128;    // [16 tok][8] output staging
    const uint2* btab = reinterpret_cast<const uint2*>(sm);
    const int warpGlobal = blockIdx.x * 8 + wid;

    for (int tile = warpGlobal; tile < NTILES; tile += NWARPS) {
        const int token = tile * 16 + lane;
        float x[8], cond[8];
        if (lane < 16) {
            const float4* lat4 = reinterpret_cast<const float4*>(latent);
            float4 p0 = lat4[token * 2], p1 = lat4[token * 2 + 1];
            x[0] = p0.x; x[1] = p0.y; x[2] = p0.z; x[3] = p0.w;
            x[4] = p1.x; x[5] = p1.y; x[6] = p1.z; x[7] = p1.w;
            const int cls = g_cls[(token >> 4) & (N_NODES - 1)];
            const float* sG = sm + F_G + cls * 64;
#pragma unroll
            for (int e = 0; e < 8; e++) cond[e] = 0.f;
#pragma unroll
            for (int d = 0; d < 8; d++) {
                float xd = x[d];
#pragma unroll
                for (int e = 0; e < 8; e++) cond[e] = fmaf(xd, sG[d * 8 + e], cond[e]);
            }
        }
        float logdet = 0.f;

#pragma unroll 1
        for (int blk = 0; blk < 3; blk++) {
            const int off1 = (blk & 1) ? 4 : 0;
            const int off2 = 4 - off1;
            const int tb0 = blk * 88;

            // stage in12 = [x_half | cond]
            if (lane < 16) {
#pragma unroll
                for (int q = 0; q < 4; q++) stg[lane * 16 + q] = x[off1 + q];
#pragma unroll
                for (int q = 0; q < 8; q++) stg[lane * 16 + 4 + q] = cond[q];
            }
            __syncwarp();

            // build A0 fragments (hi/lo)
            uint32_t Ah[4], Al[4];
            {
                float2 p00 = *reinterpret_cast<float2*>(stg + r * 16 + qq * 2);
                float2 p10 = *reinterpret_cast<float2*>(stg + (r + 8) * 16 + qq * 2);
                float2 p08 = make_float2(0.f, 0.f), p18 = p08;
                if (qq < 2) {
                    p08 = *reinterpret_cast<float2*>(stg + r * 16 + qq * 2 + 8);
                    p18 = *reinterpret_cast<float2*>(stg + (r + 8) * 16 + qq * 2 + 8);
                }
                splitpack(p00.x, p00.y, Ah[0], Al[0]);
                splitpack(p10.x, p10.y, Ah[1], Al[1]);
                splitpack(p08.x, p08.y, Ah[2], Al[2]);
                splitpack(p18.x, p18.y, Ah[3], Al[3]);
            }
            __syncwarp();

            // ---- layer 0: 12(->16) -> 64 ----
            uint32_t A1h[16], A1l[16];
#pragma unroll
            for (int jn = 0; jn < 8; jn++) {
                float2 bia = *reinterpret_cast<const float2*>(sm + F_B0 + blk * 64 + jn * 8 + qq * 2);
                float D[4] = { bia.x, bia.y, bia.x, bia.y };
                const uint2* tb = btab + (tb0 + jn * 2) * 32 + lane;
                uint2 bh = tb[0], bl = tb[32];
                MMA4(D, Ah, bh.x, bh.y);
                MMA4(D, Ah, bl.x, bl.y);
                MMA4(D, Al, bh.x, bh.y);
                float h0 = fmaxf(D[0], 0.f), h1 = fmaxf(D[1], 0.f);
                float h2 = fmaxf(D[2], 0.f), h3 = fmaxf(D[3], 0.f);
                splitpack(h0, h1, A1h[jn * 2],     A1l[jn * 2]);
                splitpack(h2, h3, A1h[jn * 2 + 1], A1l[jn * 2 + 1]);
            }

            // ---- layer 1: 64 -> 64 ----
            uint32_t A2h[16], A2l[16];
#pragma unroll
            for (int jn = 0; jn < 8; jn++) {
                float2 bia = *reinterpret_cast<const float2*>(sm + F_B1 + blk * 64 + jn * 8 + qq * 2);
                float D[4] = { bia.x, bia.y, bia.x, bia.y };
#pragma unroll
                for (int kb = 0; kb < 4; kb++) {
                    const uint2* tb = btab + (tb0 + 16 + (jn * 4 + kb) * 2) * 32 + lane;
                    uint2 bh = tb[0], bl = tb[32];
                    MMA4(D, (A1h + 4 * kb), bh.x, bh.y);
                    MMA4(D, (A1h + 4 * kb), bl.x, bl.y);
                    MMA4(D, (A1l + 4 * kb), bh.x, bh.y);
                }
                float h0 = fmaxf(D[0], 0.f), h1 = fmaxf(D[1], 0.f);
                float h2 = fmaxf(D[2], 0.f), h3 = fmaxf(D[3], 0.f);
                splitpack(h0, h1, A2h[jn * 2],     A2l[jn * 2]);
                splitpack(h2, h3, A2h[jn * 2 + 1], A2l[jn * 2 + 1]);
            }

            // ---- layer 2: 64 -> 8 ----
            {
                float2 bia = *reinterpret_cast<const float2*>(sm + F_B2 + blk * 8 + qq * 2);
                float D[4] = { bia.x, bia.y, bia.x, bia.y };
#pragma unroll
                for (int kb = 0; kb < 4; kb++) {
                    const uint2* tb = btab + (tb0 + 80 + kb * 2) * 32 + lane;
                    uint2 bh = tb[0], bl = tb[32];
                    MMA4(D, (A2h + 4 * kb), bh.x, bh.y);
                    MMA4(D, (A2h + 4 * kb), bl.x, bl.y);
                    MMA4(D, (A2l + 4 * kb), bh.x, bh.y);
                }
                sD[r * 8 + qq * 2]           = D[0];
                sD[r * 8 + qq * 2 + 1]       = D[1];
                sD[(r + 8) * 8 + qq * 2]     = D[2];
                sD[(r + 8) * 8 + qq * 2 + 1] = D[3];
            }
            __syncwarp();

            // coupling update (lanes < 16, one token each)
            if (lane < 16) {
                float4 oa = *reinterpret_cast<float4*>(sD + lane * 8);
                float4 ob = *reinterpret_cast<float4*>(sD + lane * 8 + 4);
                float s0 = tanhf(oa.x), s1 = tanhf(oa.y), s2 = tanhf(oa.z), s3 = tanhf(oa.w);
                logdet += s0 + s1 + s2 + s3;
                x[off2 + 0] = x[off2 + 0] * expf(s0) + ob.x;
                x[off2 + 1] = x[off2 + 1] * expf(s1) + ob.y;
                x[off2 + 2] = x[off2 + 2] * expf(s2) + ob.z;
                x[off2 + 3] = x[off2 + 3] * expf(s3) + ob.w;
            }
            __syncwarp();
        }

        if (lane < 16) {
            float ss = 0.f;
#pragma unroll
            for (int q = 0; q < 8; q++) ss += x[q] * x[q];
            out[token] = -0.5f * ss - 7.3515082656f + logdet;
        }
    }
}

// ============================================================================
extern "C" void kernel_launch(void* const* d_in, const int* in_sizes, int n_in,
                              void* d_out, int out_size)
{
    const float* latent = (const float*)d_in[0];
    const float* koop   = (const float*)d_in[1];
    const float* comm   = (const float*)d_in[2];
    const float* W0     = (const float*)d_in[3];
    const float* b0     = (const float*)d_in[4];
    const float* W1     = (const float*)d_in[5];
    const float* b1     = (const float*)d_in[6];
    const float* W2     = (const float*)d_in[7];
    const float* b2     = (const float*)d_in[8];
    float* out = (float*)d_out;

    eig_vals_kernel<<<C_COMM, 1>>>(koop);
    horner_kernel<<<C_COMM, 64>>>(koop);
    argmax_kernel<<<N_NODES / 256, 256>>>(comm);
    wprep_kernel<<<3, 256>>>(W0, W1, W2);

    (void)cudaFuncSetAttribute(main_kernel,
                               cudaFuncAttributeMaxDynamicSharedMemorySize, SMEM_TOTAL);
    main_kernel<<<GRID_CTAS, 256, SMEM_TOTAL>>>(latent, b0, b1, b2, out);
}

// round 9
// speedup vs baseline: 3.2585x; 1.1114x over previous
#include <cuda_runtime.h>
#include <cuda_bf16.h>
#include <math.h>
#include <stdint.h>

#define N_NODES 4096
#define C_COMM  32
#define TOK     (32*4096*16)
#define NTILES  (TOK/16)        // 131072 warp-tiles of 16 tokens
#define GRID_CTAS 296
#define NWARPS  (GRID_CTAS*8)   // 2368

// ---------------- device scratch ----------------
__device__ float  g_G[C_COMM * 64];
__device__ int    g_cls[N_NODES];
__device__ double g_zr[C_COMM*8], g_zi[C_COMM*8], g_cr[C_COMM*8], g_ci[C_COMM*8];
// B-fragment tables: [3 blocks][88 pos][32 lanes] x uint2  (67584 B)
__device__ uint2  g_btab[3 * 88 * 32];

// ---------------- smem float layout ----------------
#define F_BTAB 0          // 16896 floats (btab as raw)
#define F_B0   16896      // 192
#define F_B1   17088      // 192
#define F_B2   17280      // 24
#define F_G    17304      // 2048
#define F_SIN  19352      // 8 warps x 16 x 16
#define F_SD   21400      // 8 warps x 16 x 8
#define SMEM_FLOATS 22424
#define SMEM_TOTAL  (SMEM_FLOATS*4)

#define MMA4(D, A, B0, B1) asm volatile( \
    "mma.sync.aligned.m16n8k16.row.col.f32.bf16.bf16.f32 " \
    "{%0,%1,%2,%3},{%4,%5,%6,%7},{%8,%9},{%0,%1,%2,%3};" \
    : "+f"((D)[0]), "+f"((D)[1]), "+f"((D)[2]), "+f"((D)[3]) \
    : "r"((A)[0]), "r"((A)[1]), "r"((A)[2]), "r"((A)[3]), "r"(B0), "r"(B1))

// split v = hi + lo (hi = truncate-to-bf16, lo = bf16 residual); pack pairs
__device__ __forceinline__ void splitpack(float v0, float v1, uint32_t& hi, uint32_t& lo) {
    uint32_t u0 = __float_as_uint(v0), u1 = __float_as_uint(v1);
    hi = __byte_perm(u0, u1, 0x7632);
    float h0 = __uint_as_float(u0 & 0xFFFF0000u);
    float h1 = __uint_as_float(u1 & 0xFFFF0000u);
    asm("cvt.rn.bf16x2.f32 %0, %1, %2;" : "=r"(lo) : "f"(v1 - h1), "f"(v0 - h0));
}

// ============================================================================
// Kernel 1a: fp32 Hessenberg + Francis QR eigenvalues (reference uses
// complex64 eig, so fp32 matches its noise floor), then fp64 mask +
// node perturbation + Newton divided differences.
// ============================================================================
__global__ void eig_vals_kernel(const float* __restrict__ koop)
{
    int c = blockIdx.x;
    if (threadIdx.x != 0) return;
    float a[8][8];
    for (int i = 0; i < 8; i++)
        for (int j = 0; j < 8; j++)
            a[i][j] = koop[c * 64 + i * 8 + j];
    // Householder -> Hessenberg (fp32)
    for (int k = 0; k < 6; k++) {
        float nx = 0.f;
        for (int i = k + 1; i < 8; i++) nx += a[i][k] * a[i][k];
        nx = sqrtf(nx);
        if (nx < 1e-30f) continue;
        float x0 = a[k + 1][k];
        float alpha = (x0 >= 0.f) ? -nx : nx;
        float v[8];
        for (int i = 0; i < 8; i++) v[i] = 0.f;
        v[k + 1] = x0 - alpha;
        for (int i = k + 2; i < 8; i++) v[i] = a[i][k];
        float vv = 0.f;
        for (int i = k + 1; i < 8; i++) vv += v[i] * v[i];
        if (vv < 1e-30f) continue;
        float beta = 2.f / vv;
        for (int j = 0; j < 8; j++) {
            float s = 0.f;
            for (int i = k + 1; i < 8; i++) s += v[i] * a[i][j];
            s *= beta;
            for (int i = k + 1; i < 8; i++) a[i][j] -= v[i] * s;
        }
        for (int i = 0; i < 8; i++) {
            float s = 0.f;
            for (int j = k + 1; j < 8; j++) s += a[i][j] * v[j];
            s *= beta;
            for (int j = k + 1; j < 8; j++) a[i][j] -= s * v[j];
        }
    }
    // Francis double-shift QR (fp32, hard-capped)
    float wr[8], wi[8];
    float anorm = 0.f;
    for (int i = 0; i < 8; i++) {
        int j0 = (i - 1 > 0) ? (i - 1) : 0;
        for (int j = j0; j < 8; j++) anorm += fabsf(a[i][j]);
    }
    const float EPSF = 1.1920929e-07f;
    int nn = 7; float t = 0.f; int guard = 0;
    while (nn >= 0 && guard < 2000) {
        int its = 0, l = 0;
        do {
            guard++;
            if (guard >= 2000) { wr[nn] = a[nn][nn] + t; wi[nn] = 0.f; nn--; break; }
            for (l = nn; l >= 1; l--) {
                float s = fabsf(a[l - 1][l - 1]) + fabsf(a[l][l]);
                if (s == 0.f) s = anorm;
                if (fabsf(a[l][l - 1]) <= EPSF * s) { a[l][l - 1] = 0.f; break; }
            }
            if (l < 0) l = 0;
            float x = a[nn][nn];
            if (l == nn) { wr[nn] = x + t; wi[nn] = 0.f; nn--; }
            else {
                float y = a[nn - 1][nn - 1];
                float w = a[nn][nn - 1] * a[nn - 1][nn];
                if (l == nn - 1) {
                    float p = 0.5f * (y - x);
                    float q = p * p + w;
                    float z = sqrtf(fabsf(q));
                    x += t;
                    if (q >= 0.f) {
                        z = p + ((p >= 0.f) ? z : -z);
                        wr[nn - 1] = wr[nn] = x + z;
                        if (z != 0.f) wr[nn] = x - w / z;
                        wi[nn - 1] = wi[nn] = 0.f;
                    } else {
                        wr[nn - 1] = wr[nn] = x + p;
                        wi[nn] = z; wi[nn - 1] = -z;
                    }
                    nn -= 2;
                } else {
                    float p = 0.f, q = 0.f, r = 0.f, z, s, u, v;
                    if (its == 10 || its == 20) {
                        t += x;
                        for (int i = 0; i <= nn; i++) a[i][i] -= x;
                        s = fabsf(a[nn][nn - 1]) + fabsf(a[nn - 1][nn - 2]);
                        y = x = 0.75f * s;
                        w = -0.4375f * s * s;
                    }
                    its++;
                    if (its > 50) { wr[nn] = a[nn][nn] + t; wi[nn] = 0.f; nn--; break; }
                    int m;
                    for (m = nn - 2; m >= l; m--) {
                        z = a[m][m]; r = x - z; s = y - z;
                        p = (r * s - w) / a[m + 1][m] + a[m][m + 1];
                        q = a[m + 1][m + 1] - z - r - s;
                        r = a[m + 2][m + 1];
                        s = fabsf(p) + fabsf(q) + fabsf(r);
                        p /= s; q /= s; r /= s;
                        if (m == l) break;
                        u = fabsf(a[m][m - 1]) * (fabsf(q) + fabsf(r));
                        v = fabsf(p) * (fabsf(a[m - 1][m - 1]) + fabsf(z) + fabsf(a[m + 1][m + 1]));
                        if (u <= EPSF * v) break;
                    }
                    for (int i = m + 2; i <= nn; i++) {
                        a[i][i - 2] = 0.f;
                        if (i != m + 2) a[i][i - 3] = 0.f;
                    }
                    for (int k = m; k <= nn - 1; k++) {
                        if (k != m) {
                            p = a[k][k - 1]; q = a[k + 1][k - 1];
                            r = (k != nn - 1) ? a[k + 2][k - 1] : 0.f;
                            x = fabsf(p) + fabsf(q) + fabsf(r);
                            if (x != 0.f) { p /= x; q /= x; r /= x; }
                        }
                        s = sqrtf(p * p + q * q + r * r);
                        if (p < 0.f) s = -s;
                        if (s != 0.f) {
                            if (k == m) { if (l != m) a[k][k - 1] = -a[k][k - 1]; }
                            else a[k][k - 1] = -s * x;
                            p += s; x = p / s; y = q / s; z = r / s; q /= p; r /= p;
                            for (int j = k; j <= nn; j++) {
                                float pp = a[k][j] + q * a[k + 1][j];
                                if (k != nn - 1) { pp += r * a[k + 2][j]; a[k + 2][j] -= pp * z; }
                                a[k + 1][j] -= pp * y;
                                a[k][j]     -= pp * x;
                            }
                            int mmin = (nn < k + 3) ? nn : (k + 3);
                            for (int i = l; i <= mmin; i++) {
                                float pp = x * a[i][k] + y * a[i][k + 1];
                                if (k != nn - 1) { pp += z * a[i][k + 2]; a[i][k + 2] -= pp * r; }
                                a[i][k + 1] -= pp * q;
                                a[i][k]     -= pp;
                            }
                        }
                    }
                }
            }
        } while (l < nn - 1);
    }
    // fp64 post-processing: mask + perturb (1e-8 needs fp64!) + divided diffs
    double zr[8], zi[8];
    for (int i = 0; i < 8; i++) { zr[i] = (double)wr[i] + 1e-10; zi[i] = (double)wi[i] + 1e-10; }
    bool mask[8]; bool any = false;
    for (int i = 0; i < 8; i++) {
        double am = sqrt(zr[i] * zr[i] + zi[i] * zi[i]);
        mask[i] = (am <= 1.1 && am >= 0.9);
        any = any || mask[i];
    }
    if (!any) for (int i = 0; i < 8; i++) mask[i] = true;
    for (int i = 1; i < 8; i++)
        for (int j = 0; j < i; j++)
            if (fabs(zr[i] - zr[j]) < 1e-9 && fabs(zi[i] - zi[j]) < 1e-9) {
                zr[i] += 1.0e-8 * (i + 1);
                zi[i] += 0.7e-8 * (i + 1);
            }
    double cr[8], ci[8];
    for (int i = 0; i < 8; i++) {
        cr[i] = mask[i] ? zr[i] : 0.0;
        ci[i] = mask[i] ? zi[i] : 0.0;
    }
    for (int j = 1; j < 8; j++)
        for (int i = 7; i >= j; i--) {
            double nr = cr[i] - cr[i - 1], ni = ci[i] - ci[i - 1];
            double dr = zr[i] - zr[i - j], di = zi[i] - zi[i - j];
            double d2 = dr * dr + di * di;
            cr[i] = (nr * dr + ni * di) / d2;
            ci[i] = (ni * dr - nr * di) / d2;
        }
    for (int i = 0; i < 8; i++) {
        g_zr[c * 8 + i] = zr[i]; g_zi[c * 8 + i] = zi[i];
        g_cr[c * 8 + i] = cr[i]; g_ci[c * 8 + i] = ci[i];
    }
}

// ============================================================================
// Kernel 1b: parallel complex Horner p(A) -> G (64 threads per matrix, fp64)
// ============================================================================
__global__ void horner_kernel(const float* __restrict__ koop)
{
    int c = blockIdx.x;
    int t = threadIdx.x;
    int i = t >> 3, j = t & 7;
    __shared__ double sA[64], sMr[64], sMi[64], szr[8], szi[8], scr[8], sci[8];
    sA[t] = (double)koop[c * 64 + t];
    if (t < 8) {
        szr[t] = g_zr[c * 8 + t]; szi[t] = g_zi[c * 8 + t];
        scr[t] = g_cr[c * 8 + t]; sci[t] = g_ci[c * 8 + t];
    }
    __syncthreads();
    double mr = (i == j) ? scr[7] : 0.0;
    double mi = (i == j) ? sci[7] : 0.0;
    sMr[t] = mr; sMi[t] = mi;
    __syncthreads();
    for (int k = 6; k >= 0; k--) {
        double tr = 0.0, ti = 0.0;
#pragma unroll
        for (int q = 0; q < 8; q++) {
            tr += sA[i * 8 + q] * sMr[q * 8 + j];
            ti += sA[i * 8 + q] * sMi[q * 8 + j];
        }
        double omr = mr, omi = mi;
        __syncthreads();
        mr = tr - (szr[k] * omr - szi[k] * omi) + ((i == j) ? scr[k] : 0.0);
        mi = ti - (szr[k] * omi + szi[k] * omr) + ((i == j) ? sci[k] : 0.0);
        sMr[t] = mr; sMi[t] = mi;
        __syncthreads();
    }
    g_G[c * 64 + t] = (float)mr;
}

// ============================================================================
// Kernel 2: community argmax
// ============================================================================
__global__ void argmax_kernel(const float* __restrict__ comm)
{
    int n = blockIdx.x * blockDim.x + threadIdx.x;
    if (n >= N_NODES) return;
    float best = comm[n * C_COMM];
    int bi = 0;
#pragma unroll
    for (int cc = 1; cc < C_COMM; cc++) {
        float v = comm[n * C_COMM + cc];
        if (v > best) { best = v; bi = cc; }
    }
    g_cls[n] = bi;
}

// ============================================================================
// Kernel 3: build per-lane B-fragment tables (hi/lo bf16, m16n8k16 layout).
// grid = (3 blocks, 11 slabs) — one 256-entry slab per CTA (latency spread).
// pos map per coupling block (88 pos): L0: jn*2+v (16) | L1: 16+(jn*4+kb)*2+v
// (64) | L2: 80+kb*2+v (8). Fragment: x = pack(W[k0][n], W[k1][n]),
// y = pack(W[k0+8][n], W[k1+8][n]); n = jn*8+lane/4, k0 = 16*kb+2*(lane%4).
// ============================================================================
__global__ void wprep_kernel(const float* __restrict__ W0,
                             const float* __restrict__ W1,
                             const float* __restrict__ W2)
{
    int blk = blockIdx.x;
    int idx = blockIdx.y * 256 + threadIdx.x;
    if (idx >= 88 * 32) return;
    {
        int pos = idx >> 5, lane = idx & 31;
        int v, jn, kb, layer;
        if (pos < 16)      { layer = 0; v = pos & 1; jn = pos >> 1; kb = 0; }
        else if (pos < 80) { int p = pos - 16; v = p & 1; int q = p >> 1; kb = q & 3; jn = q >> 2; layer = 1; }
        else               { int p = pos - 80; v = p & 1; kb = p >> 1; jn = 0; layer = 2; }
        int n = jn * 8 + (lane >> 2);
        int k0 = 16 * kb + 2 * (lane & 3);
        float w[4];
#pragma unroll
        for (int e = 0; e < 4; e++) {
            int k = k0 + (e >> 1) * 8 + (e & 1);
            float val = 0.f;
            if (layer == 0)      { if (k < 12) val = W0[blk * 768 + k * 64 + n]; }
            else if (layer == 1) { val = W1[blk * 4096 + k * 64 + n]; }
            else                 { val = W2[blk * 512 + k * 8 + n]; }
            __nv_bfloat16 bh = __float2bfloat16(val);
            if (v == 0) w[e] = __bfloat162float(bh);
            else        w[e] = __bfloat162float(__float2bfloat16(val - __bfloat162float(bh)));
        }
        uint32_t px = ((uint32_t)__bfloat16_as_ushort(__float2bfloat16(w[1])) << 16)
                    |  (uint32_t)__bfloat16_as_ushort(__float2bfloat16(w[0]));
        uint32_t py = ((uint32_t)__bfloat16_as_ushort(__float2bfloat16(w[3])) << 16)
                    |  (uint32_t)__bfloat16_as_ushort(__float2bfloat16(w[2]));
        g_btab[(blk * 88 + pos) * 32 + lane] = make_uint2(px, py);
    }
}

// ============================================================================
// Kernel 4: main fused flow via mma.sync bf16x3. Persistent, warp = 16 tokens.
// (UNCHANGED from R8 winner — protected.)
// ============================================================================
__global__ void __launch_bounds__(256, 2) main_kernel(
    const float* __restrict__ latent,
    const float* __restrict__ b0g, const float* __restrict__ b1g,
    const float* __restrict__ b2g, float* __restrict__ out)
{
    extern __shared__ float sm[];
    {
        const uint4* src = reinterpret_cast<const uint4*>(g_btab);
        uint4* dst = reinterpret_cast<uint4*>(sm);
        for (int i = threadIdx.x; i < 16896 / 4; i += 256) dst[i] = src[i];
        for (int i = threadIdx.x; i < 192;  i += 256) sm[F_B0 + i] = b0g[i];
        for (int i = threadIdx.x; i < 192;  i += 256) sm[F_B1 + i] = b1g[i];
        for (int i = threadIdx.x; i < 24;   i += 256) sm[F_B2 + i] = b2g[i];
        for (int i = threadIdx.x; i < 2048; i += 256) sm[F_G + i] = g_G[i];
    }
    __syncthreads();

    const int wid = threadIdx.x >> 5;
    const int lane = threadIdx.x & 31;
    const int r = lane >> 2, qq = lane & 3;
    float* stg = sm + F_SIN + wid * 256;
    float* sD  = sm + F_SD  + wid * 128;
    const uint2* btab = reinterpret_cast<const uint2*>(sm);
    const int warpGlobal = blockIdx.x * 8 + wid;

    for (int tile = warpGlobal; tile < NTILES; tile += NWARPS) {
        const int token = tile * 16 + lane;
        float x[8], cond[8];
        if (lane < 16) {
            const float4* lat4 = reinterpret_cast<const float4*>(latent);
            float4 p0 = lat4[token * 2], p1 = lat4[token * 2 + 1];
            x[0] = p0.x; x[1] = p0.y; x[2] = p0.z; x[3] = p0.w;
            x[4] = p1.x; x[5] = p1.y; x[6] = p1.z; x[7] = p1.w;
            const int cls = g_cls[(token >> 4) & (N_NODES - 1)];
            const float* sG = sm + F_G + cls * 64;
#pragma unroll
            for (int e = 0; e < 8; e++) cond[e] = 0.f;
#pragma unroll
            for (int d = 0; d < 8; d++) {
                float xd = x[d];
#pragma unroll
                for (int e = 0; e < 8; e++) cond[e] = fmaf(xd, sG[d * 8 + e], cond[e]);
            }
        }
        float logdet = 0.f;

#pragma unroll 1
        for (int blk = 0; blk < 3; blk++) {
            const int off1 = (blk & 1) ? 4 : 0;
            const int off2 = 4 - off1;
            const int tb0 = blk * 88;

            if (lane < 16) {
#pragma unroll
                for (int q = 0; q < 4; q++) stg[lane * 16 + q] = x[off1 + q];
#pragma unroll
                for (int q = 0; q < 8; q++) stg[lane * 16 + 4 + q] = cond[q];
            }
            __syncwarp();

            uint32_t Ah[4], Al[4];
            {
                float2 p00 = *reinterpret_cast<float2*>(stg + r * 16 + qq * 2);
                float2 p10 = *reinterpret_cast<float2*>(stg + (r + 8) * 16 + qq * 2);
                float2 p08 = make_float2(0.f, 0.f), p18 = p08;
                if (qq < 2) {
                    p08 = *reinterpret_cast<float2*>(stg + r * 16 + qq * 2 + 8);
                    p18 = *reinterpret_cast<float2*>(stg + (r + 8) * 16 + qq * 2 + 8);
                }
                splitpack(p00.x, p00.y, Ah[0], Al[0]);
                splitpack(p10.x, p10.y, Ah[1], Al[1]);
                splitpack(p08.x, p08.y, Ah[2], Al[2]);
                splitpack(p18.x, p18.y, Ah[3], Al[3]);
            }
            __syncwarp();

            // ---- layer 0: 12(->16) -> 64 ----
            uint32_t A1h[16], A1l[16];
#pragma unroll
            for (int jn = 0; jn < 8; jn++) {
                float2 bia = *reinterpret_cast<const float2*>(sm + F_B0 + blk * 64 + jn * 8 + qq * 2);
                float D[4] = { bia.x, bia.y, bia.x, bia.y };
                const uint2* tb = btab + (tb0 + jn * 2) * 32 + lane;
                uint2 bh = tb[0], bl = tb[32];
                MMA4(D, Ah, bh.x, bh.y);
                MMA4(D, Ah, bl.x, bl.y);
                MMA4(D, Al, bh.x, bh.y);
                float h0 = fmaxf(D[0], 0.f), h1 = fmaxf(D[1], 0.f);
                float h2 = fmaxf(D[2], 0.f), h3 = fmaxf(D[3], 0.f);
                splitpack(h0, h1, A1h[jn * 2],     A1l[jn * 2]);
                splitpack(h2, h3, A1h[jn * 2 + 1], A1l[jn * 2 + 1]);
            }

            // ---- layer 1: 64 -> 64 ----
            uint32_t A2h[16], A2l[16];
#pragma unroll
            for (int jn = 0; jn < 8; jn++) {
                float2 bia = *reinterpret_cast<const float2*>(sm + F_B1 + blk * 64 + jn * 8 + qq * 2);
                float D[4] = { bia.x, bia.y, bia.x, bia.y };
#pragma unroll
                for (int kb = 0; kb < 4; kb++) {
                    const uint2* tb = btab + (tb0 + 16 + (jn * 4 + kb) * 2) * 32 + lane;
                    uint2 bh = tb[0], bl = tb[32];
                    MMA4(D, (A1h + 4 * kb), bh.x, bh.y);
                    MMA4(D, (A1h + 4 * kb), bl.x, bl.y);
                    MMA4(D, (A1l + 4 * kb), bh.x, bh.y);
                }
                float h0 = fmaxf(D[0], 0.f), h1 = fmaxf(D[1], 0.f);
                float h2 = fmaxf(D[2], 0.f), h3 = fmaxf(D[3], 0.f);
                splitpack(h0, h1, A2h[jn * 2],     A2l[jn * 2]);
                splitpack(h2, h3, A2h[jn * 2 + 1], A2l[jn * 2 + 1]);
            }

            // ---- layer 2: 64 -> 8 ----
            {
                float2 bia = *reinterpret_cast<const float2*>(sm + F_B2 + blk * 8 + qq * 2);
                float D[4] = { bia.x, bia.y, bia.x, bia.y };
#pragma unroll
                for (int kb = 0; kb < 4; kb++) {
                    const uint2* tb = btab + (tb0 + 80 + kb * 2) * 32 + lane;
                    uint2 bh = tb[0], bl = tb[32];
                    MMA4(D, (A2h + 4 * kb), bh.x, bh.y);
                    MMA4(D, (A2h + 4 * kb), bl.x, bl.y);
                    MMA4(D, (A2l + 4 * kb), bh.x, bh.y);
                }
                sD[r * 8 + qq * 2]           = D[0];
                sD[r * 8 + qq * 2 + 1]       = D[1];
                sD[(r + 8) * 8 + qq * 2]     = D[2];
                sD[(r + 8) * 8 + qq * 2 + 1] = D[3];
            }
            __syncwarp();

            if (lane < 16) {
                float4 oa = *reinterpret_cast<float4*>(sD + lane * 8);
                float4 ob = *reinterpret_cast<float4*>(sD + lane * 8 + 4);
                float s0 = tanhf(oa.x), s1 = tanhf(oa.y), s2 = tanhf(oa.z), s3 = tanhf(oa.w);
                logdet += s0 + s1 + s2 + s3;
                x[off2 + 0] = x[off2 + 0] * expf(s0) + ob.x;
                x[off2 + 1] = x[off2 + 1] * expf(s1) + ob.y;
                x[off2 + 2] = x[off2 + 2] * expf(s2) + ob.z;
                x[off2 + 3] = x[off2 + 3] * expf(s3) + ob.w;
            }
            __syncwarp();
        }

        if (lane < 16) {
            float ss = 0.f;
#pragma unroll
            for (int q = 0; q < 8; q++) ss += x[q] * x[q];
            out[token] = -0.5f * ss - 7.3515082656f + logdet;
        }
    }
}

// ============================================================================
extern "C" void kernel_launch(void* const* d_in, const int* in_sizes, int n_in,
                              void* d_out, int out_size)
{
    const float* latent = (const float*)d_in[0];
    const float* koop   = (const float*)d_in[1];
    const float* comm   = (const float*)d_in[2];
    const float* W0     = (const float*)d_in[3];
    const float* b0     = (const float*)d_in[4];
    const float* W1     = (const float*)d_in[5];
    const float* b1     = (const float*)d_in[6];
    const float* W2     = (const float*)d_in[7];
    const float* b2     = (const float*)d_in[8];
    float* out = (float*)d_out;

    eig_vals_kernel<<<C_COMM, 1>>>(koop);
    horner_kernel<<<C_COMM, 64>>>(koop);
    argmax_kernel<<<N_NODES / 256, 256>>>(comm);
    wprep_kernel<<<dim3(3, 11), 256>>>(W0, W1, W2);

    (void)cudaFuncSetAttribute(main_kernel,
                               cudaFuncAttributeMaxDynamicSharedMemorySize, SMEM_TOTAL);
    main_kernel<<<GRID_CTAS, 256, SMEM_TOTAL>>>(latent, b0, b1, b2, out);
}